// round 1
// baseline (speedup 1.0000x reference)
#include <cuda_runtime.h>
#include <cuda_bf16.h>

// Problem constants
#define B_   4
#define T_   1024
#define HW_  1296            // 27*48
#define NBINS_ 512
#define LOOKUP_ 101
#define PAD_ 50
#define ODIM_ 128
#define TT_  32              // centers per block in band kernel

// Scratch: normalized histograms, (B*T, 512) fp32 = 8 MB
__device__ float g_hist[B_ * T_ * NBINS_];

// ---------------------------------------------------------------------------
// Kernel 1: per-frame 512-bin RGB histogram + L2 normalize
// grid = 4096 blocks (one per frame), 256 threads
// ---------------------------------------------------------------------------
__global__ __launch_bounds__(256) void hist_kernel(const int* __restrict__ frames)
{
    __shared__ unsigned int h[NBINS_];
    __shared__ float red[8];

    const int bt = blockIdx.x;
    const int tid = threadIdx.x;
    const int* f = frames + (size_t)bt * HW_ * 3;

    #pragma unroll
    for (int i = tid; i < NBINS_; i += 256) h[i] = 0u;
    __syncthreads();

    // 1296 pixels = 324 groups of 4 pixels (12 ints = 3 * int4, 16B aligned)
    for (int grp = tid; grp < HW_ / 4; grp += 256) {
        const int4* p4 = (const int4*)(f + grp * 12);
        int4 v0 = p4[0];
        int4 v1 = p4[1];
        int4 v2 = p4[2];
        int b0 = ((v0.x >> 5) << 6) | ((v0.y >> 5) << 3) | (v0.z >> 5);
        int b1 = ((v0.w >> 5) << 6) | ((v1.x >> 5) << 3) | (v1.y >> 5);
        int b2 = ((v1.z >> 5) << 6) | ((v1.w >> 5) << 3) | (v2.x >> 5);
        int b3 = ((v2.y >> 5) << 6) | ((v2.z >> 5) << 3) | (v2.w >> 5);
        atomicAdd(&h[b0], 1u);
        atomicAdd(&h[b1], 1u);
        atomicAdd(&h[b2], 1u);
        atomicAdd(&h[b3], 1u);
    }
    __syncthreads();

    // sum of squares
    float s = 0.f;
    #pragma unroll
    for (int i = tid; i < NBINS_; i += 256) {
        float v = (float)h[i];
        s += v * v;
    }
    #pragma unroll
    for (int o = 16; o; o >>= 1) s += __shfl_down_sync(0xffffffffu, s, o);
    if ((tid & 31) == 0) red[tid >> 5] = s;
    __syncthreads();
    if (tid == 0) {
        float t = 0.f;
        #pragma unroll
        for (int i = 0; i < 8; i++) t += red[i];
        red[0] = 1.0f / fmaxf(sqrtf(t), 1e-12f);
    }
    __syncthreads();
    const float inv = red[0];

    float* dst = g_hist + (size_t)bt * NBINS_;
    #pragma unroll
    for (int i = tid; i < NBINS_; i += 256) dst[i] = (float)h[i] * inv;
}

// ---------------------------------------------------------------------------
// Kernel 2: banded similarity (only the +-50 diagonal) + FC(101->128) + ReLU
// grid = (T/TT, B) = (32, 4), 256 threads.
//
// Thread layout for band phase:
//   s  = tid & 15         k-subgroup: owns k = k32*16 + s (interleaved -> no
//                         smem bank conflicts on the neighbor row)
//   g  = (tid >> 4) & 7   center group: owns centers c = g + 8*m, m=0..3
//   nb = tid >> 7         neighbor slot (2 neighbor rows per iteration)
// X (center rows) live in registers: 4 centers x 32 k = 128 regs/thread.
// ---------------------------------------------------------------------------
__global__ __launch_bounds__(256, 1) void band_fc_kernel(
    const float* __restrict__ fc_w,   // (101,128)
    const float* __restrict__ fc_b,   // (128,)
    float* __restrict__ out)          // (B,T,128)
{
    __shared__ float Ys[2][NBINS_];
    __shared__ float win[TT_][104];   // padded to 104

    const int tid = threadIdx.x;
    const int b  = blockIdx.y;
    const int t0 = blockIdx.x * TT_;
    const float* histb = g_hist + (size_t)b * T_ * NBINS_;

    // zero the window (covers out-of-range l / clipped neighbors)
    for (int i = tid; i < TT_ * 104; i += 256) (&win[0][0])[i] = 0.f;

    const int s  = tid & 15;
    const int g  = (tid >> 4) & 7;
    const int nb = tid >> 7;

    // Load center rows into registers (interleaved k ownership)
    float x[4][32];
    #pragma unroll
    for (int m = 0; m < 4; m++) {
        const float* row = histb + (size_t)(t0 + g + 8 * m) * NBINS_;
        #pragma unroll
        for (int k = 0; k < 32; k++) x[m][k] = row[k * 16 + s];
    }
    __syncthreads();

    // Band loop: neighbors j in [t0-50, t0+TT+49], 2 per iteration
    for (int jb = t0 - PAD_; jb < t0 + TT_ + PAD_; jb += 2) {
        const int j = jb + nb;
        const bool valid = (j >= 0) && (j < T_);

        // cooperative load of 2 neighbor rows (1024 floats / 256 thr = float4)
        {
            const int idx = tid * 4;           // 0..1023
            const int jj  = jb + (idx >> 9);
            const int off = idx & (NBINS_ - 1);
            float4 v = make_float4(0.f, 0.f, 0.f, 0.f);
            if (jj >= 0 && jj < T_)
                v = *(const float4*)(histb + (size_t)jj * NBINS_ + off);
            *(float4*)(&Ys[idx >> 9][off]) = v;
        }
        __syncthreads();

        float a0 = 0.f, a1 = 0.f, a2 = 0.f, a3 = 0.f;
        #pragma unroll
        for (int k = 0; k < 32; k++) {
            const float y = Ys[nb][k * 16 + s];
            a0 += x[0][k] * y;
            a1 += x[1][k] * y;
            a2 += x[2][k] * y;
            a3 += x[3][k] * y;
        }
        // reduce over s (16 contiguous lanes per half-warp)
        #pragma unroll
        for (int o = 8; o; o >>= 1) {
            a0 += __shfl_down_sync(0xffffffffu, a0, o);
            a1 += __shfl_down_sync(0xffffffffu, a1, o);
            a2 += __shfl_down_sync(0xffffffffu, a2, o);
            a3 += __shfl_down_sync(0xffffffffu, a3, o);
        }
        if (s == 0 && valid) {
            float acc[4] = {a0, a1, a2, a3};
            #pragma unroll
            for (int m = 0; m < 4; m++) {
                const int c = g + 8 * m;
                const int l = j - (t0 + c) + PAD_;
                if (l >= 0 && l < LOOKUP_) win[c][l] = acc[m];
            }
        }
        __syncthreads();
    }

    // FC phase: out[b, t0+c, o] = relu(bias[o] + sum_l win[c][l] * fc_w[l,o])
    const int o  = tid & 127;
    const int ch = tid >> 7;          // 0..1
    const float bias = fc_b[o];

    for (int cb = 0; cb < TT_; cb += 8) {
        const int c0 = cb + ch * 4;   // this thread: centers c0..c0+3
        float acc0 = bias, acc1 = bias, acc2 = bias, acc3 = bias;
        for (int l = 0; l < LOOKUP_; l++) {
            const float w = fc_w[l * ODIM_ + o];
            acc0 += win[c0 + 0][l] * w;
            acc1 += win[c0 + 1][l] * w;
            acc2 += win[c0 + 2][l] * w;
            acc3 += win[c0 + 3][l] * w;
        }
        float* op = out + ((size_t)b * T_ + t0) * ODIM_ + o;
        op[(size_t)(c0 + 0) * ODIM_] = fmaxf(acc0, 0.f);
        op[(size_t)(c0 + 1) * ODIM_] = fmaxf(acc1, 0.f);
        op[(size_t)(c0 + 2) * ODIM_] = fmaxf(acc2, 0.f);
        op[(size_t)(c0 + 3) * ODIM_] = fmaxf(acc3, 0.f);
    }
}

// ---------------------------------------------------------------------------
extern "C" void kernel_launch(void* const* d_in, const int* in_sizes, int n_in,
                              void* d_out, int out_size)
{
    const int*   frames = (const int*)d_in[0];
    const float* fc_w   = (const float*)d_in[1];
    const float* fc_b   = (const float*)d_in[2];
    float*       out    = (float*)d_out;

    hist_kernel<<<B_ * T_, 256>>>(frames);

    dim3 grid(T_ / TT_, B_);
    band_fc_kernel<<<grid, 256>>>(fc_w, fc_b, out);
}

// round 2
// speedup vs baseline: 1.4015x; 1.4015x over previous
#include <cuda_runtime.h>
#include <cuda_bf16.h>
#include <mma.h>

using namespace nvcuda;

// Problem constants
#define B_     4
#define T_     1024
#define HW_    1296            // 27*48
#define NBINS_ 512
#define LOOKUP_ 101
#define PAD_   50
#define ODIM_  128
#define TT_    32              // centers per block
#define JT_    144             // padded neighbor range (9 wmma n-tiles of 16)
#define KC_    32              // k-chunk
#define NCH_   (NBINS_ / KC_)  // 16 chunks
#define YS_LD  36              // padded smem row
#define SIMS_LD 148
#define NTHREADS_ 288          // 9 warps

// Scratch: normalized histograms, (B*T, 512) fp32 = 8 MB (L2-resident)
__device__ float g_hist[B_ * T_ * NBINS_];

// ---------------------------------------------------------------------------
// Kernel 1: per-frame 512-bin RGB histogram + L2 normalize (unchanged)
// ---------------------------------------------------------------------------
__global__ __launch_bounds__(256) void hist_kernel(const int* __restrict__ frames)
{
    __shared__ unsigned int h[NBINS_];
    __shared__ float red[8];

    const int bt = blockIdx.x;
    const int tid = threadIdx.x;
    const int* f = frames + (size_t)bt * HW_ * 3;

    #pragma unroll
    for (int i = tid; i < NBINS_; i += 256) h[i] = 0u;
    __syncthreads();

    for (int grp = tid; grp < HW_ / 4; grp += 256) {
        const int4* p4 = (const int4*)(f + grp * 12);
        int4 v0 = p4[0];
        int4 v1 = p4[1];
        int4 v2 = p4[2];
        int b0 = ((v0.x >> 5) << 6) | ((v0.y >> 5) << 3) | (v0.z >> 5);
        int b1 = ((v0.w >> 5) << 6) | ((v1.x >> 5) << 3) | (v1.y >> 5);
        int b2 = ((v1.z >> 5) << 6) | ((v1.w >> 5) << 3) | (v2.x >> 5);
        int b3 = ((v2.y >> 5) << 6) | ((v2.z >> 5) << 3) | (v2.w >> 5);
        atomicAdd(&h[b0], 1u);
        atomicAdd(&h[b1], 1u);
        atomicAdd(&h[b2], 1u);
        atomicAdd(&h[b3], 1u);
    }
    __syncthreads();

    float s = 0.f;
    #pragma unroll
    for (int i = tid; i < NBINS_; i += 256) {
        float v = (float)h[i];
        s += v * v;
    }
    #pragma unroll
    for (int o = 16; o; o >>= 1) s += __shfl_down_sync(0xffffffffu, s, o);
    if ((tid & 31) == 0) red[tid >> 5] = s;
    __syncthreads();
    if (tid == 0) {
        float t = 0.f;
        #pragma unroll
        for (int i = 0; i < 8; i++) t += red[i];
        red[0] = 1.0f / fmaxf(sqrtf(t), 1e-12f);
    }
    __syncthreads();
    const float inv = red[0];

    float* dst = g_hist + (size_t)bt * NBINS_;
    #pragma unroll
    for (int i = tid; i < NBINS_; i += 256) dst[i] = (float)h[i] * inv;
}

// ---------------------------------------------------------------------------
// Kernel 2: banded similarity via TF32 wmma (m16n16k8) + FC(101->128) + ReLU
//
// Per block: centers m = t0..t0+31 (M=32), neighbors j = t0-50+n, n in [0,144)
// (N=144, only 132 used), K = 512. A rows are a subset of B rows, so a single
// smem tile Ys[144][KC] serves both operands per k-chunk:
//   A(m,k) = Ys[m+50][k]  (row_major),  B(k,n) = Ys[n][k]  (col_major).
// Out-of-range j rows load as zero -> band edges exact with no masking.
// Epilogue: win[c][l] = sims[c][c+l]; FC + ReLU written straight to out.
// ---------------------------------------------------------------------------
__global__ __launch_bounds__(NTHREADS_) void band_fc_wmma(
    const float* __restrict__ fc_w,   // (101,128)
    const float* __restrict__ fc_b,   // (128,)
    float* __restrict__ out)          // (B,T,128)
{
    __shared__ float Ys[JT_][YS_LD];       // 144 x 36 fp32 (tf32-rounded)
    __shared__ float sims[TT_][SIMS_LD];   // 32 x 148 fp32

    const int tid  = threadIdx.x;
    const int warp = tid >> 5;
    const int b    = blockIdx.y;
    const int t0   = blockIdx.x * TT_;
    const float* histb = g_hist + (size_t)b * T_ * NBINS_;

    const int n0 = warp * 16;              // this warp's n-tile base (0..128)

    wmma::fragment<wmma::matrix_a, 16, 16, 8, wmma::precision::tf32, wmma::row_major> fa;
    wmma::fragment<wmma::matrix_b, 16, 16, 8, wmma::precision::tf32, wmma::col_major> fb;
    wmma::fragment<wmma::accumulator, 16, 16, 8, float> acc0, acc1;
    wmma::fill_fragment(acc0, 0.0f);
    wmma::fill_fragment(acc1, 0.0f);

    // Register prefetch of one k-chunk: 144 rows x 32 floats = 1152 float4,
    // exactly 4 per thread.
    float4 pf[4];

    auto load_chunk = [&](int c) {
        #pragma unroll
        for (int u = 0; u < 4; u++) {
            const int i = tid + u * NTHREADS_;   // 0..1151
            const int n = i >> 3;
            const int f = i & 7;
            const int j = t0 - PAD_ + n;
            float4 v = make_float4(0.f, 0.f, 0.f, 0.f);
            if (j >= 0 && j < T_)
                v = *(const float4*)(histb + (size_t)j * NBINS_ + c * KC_ + f * 4);
            pf[u] = v;
        }
    };

    auto store_chunk = [&]() {
        #pragma unroll
        for (int u = 0; u < 4; u++) {
            const int i = tid + u * NTHREADS_;
            const int n = i >> 3;
            const int f = i & 7;
            float4 v = pf[u];
            v.x = wmma::__float_to_tf32(v.x);
            v.y = wmma::__float_to_tf32(v.y);
            v.z = wmma::__float_to_tf32(v.z);
            v.w = wmma::__float_to_tf32(v.w);
            *(float4*)(&Ys[n][f * 4]) = v;     // 16B aligned: (36n+4f)*4
        }
    };

    load_chunk(0);

    for (int c = 0; c < NCH_; c++) {
        __syncthreads();                       // prior chunk fully consumed
        store_chunk();
        __syncthreads();                       // Ys ready
        if (c < NCH_ - 1) load_chunk(c + 1);   // LDGs overlap with HMMA below

        #pragma unroll
        for (int kk = 0; kk < KC_ / 8; kk++) {
            wmma::load_matrix_sync(fb, &Ys[n0][kk * 8], YS_LD);
            wmma::load_matrix_sync(fa, &Ys[PAD_][kk * 8], YS_LD);        // m 0..15
            wmma::mma_sync(acc0, fa, fb, acc0);
            wmma::load_matrix_sync(fa, &Ys[PAD_ + 16][kk * 8], YS_LD);   // m 16..31
            wmma::mma_sync(acc1, fa, fb, acc1);
        }
    }

    __syncthreads();
    wmma::store_matrix_sync(&sims[0][n0],  acc0, SIMS_LD, wmma::mem_row_major);
    wmma::store_matrix_sync(&sims[16][n0], acc1, SIMS_LD, wmma::mem_row_major);
    __syncthreads();

    // FC + ReLU: out[b, t0+c, o] = relu(fc_b[o] + sum_l sims[c][c+l] * fc_w[l,o])
    if (tid < 256) {
        const int o    = tid & 127;
        const int half = tid >> 7;             // centers half*16 .. half*16+15
        const int cb   = half * 16;
        const float bias = fc_b[o];

        float acc[16];
        #pragma unroll
        for (int cc = 0; cc < 16; cc++) acc[cc] = bias;

        for (int l = 0; l < LOOKUP_; l++) {
            const float w = fc_w[l * ODIM_ + o];
            #pragma unroll
            for (int cc = 0; cc < 16; cc++)
                acc[cc] += sims[cb + cc][cb + cc + l] * w;   // broadcast LDS
        }

        float* op = out + ((size_t)b * T_ + t0 + cb) * ODIM_ + o;
        #pragma unroll
        for (int cc = 0; cc < 16; cc++)
            op[(size_t)cc * ODIM_] = fmaxf(acc[cc], 0.f);
    }
}

// ---------------------------------------------------------------------------
extern "C" void kernel_launch(void* const* d_in, const int* in_sizes, int n_in,
                              void* d_out, int out_size)
{
    const int*   frames = (const int*)d_in[0];
    const float* fc_w   = (const float*)d_in[1];
    const float* fc_b   = (const float*)d_in[2];
    float*       out    = (float*)d_out;

    hist_kernel<<<B_ * T_, 256>>>(frames);

    dim3 grid(T_ / TT_, B_);
    band_fc_wmma<<<grid, NTHREADS_>>>(fc_w, fc_b, out);
}

// round 4
// speedup vs baseline: 1.4661x; 1.0460x over previous
#include <cuda_runtime.h>
#include <cuda_bf16.h>
#include <mma.h>

using namespace nvcuda;

// Problem constants
#define B_     4
#define T_     1024
#define HW_    1296            // 27*48
#define NBINS_ 512
#define LOOKUP_ 101
#define PAD_   50
#define ODIM_  128
#define TT_    32              // centers per block
#define JT_    144             // padded neighbor range (9 n-tiles of 16)
#define KC_    64              // k-chunk per stage
#define NCHG_  4               // chunks per k-group (4*64 = 256 bins/group)
#define YS_LD  68              // Ys row stride (floats)
#define SIMS_LD 148
#define WIN_LD 104             // 101 + bias row + pad to /8
#define W_LD   132
#define NTHREADS_ 576          // 18 warps: 2 k-groups x 9 n-warps

// Shared memory plan (dynamic, ~190 KB):
//  [0 .. 4*144*68)                      Ys[group][dbuf][144][68]
//     (reused after main loop:  win[32][104]  then  Wsm[104][132])
//  [ysTot .. ysTot + 2*32*148)          sims[group][32][148]
#define YS_TOT   (4 * JT_ * YS_LD)                  // 39168 floats
#define SIMS_TOT (2 * TT_ * SIMS_LD)                // 9472 floats
#define SMEM_FLOATS (YS_TOT + SIMS_TOT)
#define SMEM_BYTES  (SMEM_FLOATS * 4)

// Scratch: normalized histograms, (B*T, 512) fp32 = 8 MB (L2-resident)
__device__ float g_hist[B_ * T_ * NBINS_];

// ---------------------------------------------------------------------------
// Kernel 1: per-frame 512-bin RGB histogram + L2 normalize
// ---------------------------------------------------------------------------
__global__ __launch_bounds__(256) void hist_kernel(const int* __restrict__ frames)
{
    __shared__ unsigned int h[NBINS_];
    __shared__ float red[8];

    const int bt = blockIdx.x;
    const int tid = threadIdx.x;
    const int* f = frames + (size_t)bt * HW_ * 3;

    #pragma unroll
    for (int i = tid; i < NBINS_; i += 256) h[i] = 0u;
    __syncthreads();

    for (int grp = tid; grp < HW_ / 4; grp += 256) {
        const int4* p4 = (const int4*)(f + grp * 12);
        int4 v0 = p4[0];
        int4 v1 = p4[1];
        int4 v2 = p4[2];
        int b0 = ((v0.x >> 5) << 6) | ((v0.y >> 5) << 3) | (v0.z >> 5);
        int b1 = ((v0.w >> 5) << 6) | ((v1.x >> 5) << 3) | (v1.y >> 5);
        int b2 = ((v1.z >> 5) << 6) | ((v1.w >> 5) << 3) | (v2.x >> 5);
        int b3 = ((v2.y >> 5) << 6) | ((v2.z >> 5) << 3) | (v2.w >> 5);
        atomicAdd(&h[b0], 1u);
        atomicAdd(&h[b1], 1u);
        atomicAdd(&h[b2], 1u);
        atomicAdd(&h[b3], 1u);
    }
    __syncthreads();

    float s = 0.f;
    #pragma unroll
    for (int i = tid; i < NBINS_; i += 256) {
        float v = (float)h[i];
        s += v * v;
    }
    #pragma unroll
    for (int o = 16; o; o >>= 1) s += __shfl_down_sync(0xffffffffu, s, o);
    if ((tid & 31) == 0) red[tid >> 5] = s;
    __syncthreads();
    if (tid == 0) {
        float t = 0.f;
        #pragma unroll
        for (int i = 0; i < 8; i++) t += red[i];
        red[0] = 1.0f / fmaxf(sqrtf(t), 1e-12f);
    }
    __syncthreads();
    const float inv = red[0];

    float* dst = g_hist + (size_t)bt * NBINS_;
    #pragma unroll
    for (int i = tid; i < NBINS_; i += 256) dst[i] = (float)h[i] * inv;
}

// ---------------------------------------------------------------------------
// Kernel 2: banded similarity (tf32 wmma, k-split x2, double-buffered)
//           + FC(101->128)+bias+ReLU as a second tf32 wmma GEMM
// ---------------------------------------------------------------------------
__global__ __launch_bounds__(NTHREADS_, 1) void band_fc_v3(
    const float* __restrict__ fc_w,   // (101,128)
    const float* __restrict__ fc_b,   // (128,)
    float* __restrict__ out)          // (B,T,128)
{
    extern __shared__ float smem[];
    float* ys_base   = smem;                    // [4][144][68]
    float* sims_base = smem + YS_TOT;           // [2][32][148]

    const int tid  = threadIdx.x;
    const int b    = blockIdx.y;
    const int t0   = blockIdx.x * TT_;
    const float* histb = g_hist + (size_t)b * T_ * NBINS_;

    const int gid   = tid / 288;                // k-group 0/1 (warps 0-8 / 9-17)
    const int tidg  = tid - gid * 288;
    const int warpg = tidg >> 5;                // 0..8
    const int n0    = warpg * 16;
    const int kbase = gid * 256;

    float* Ysg   = ys_base + gid * 2 * JT_ * YS_LD;   // this group's 2 buffers
    float* simsg = sims_base + gid * TT_ * SIMS_LD;

    wmma::fragment<wmma::matrix_a, 16, 16, 8, wmma::precision::tf32, wmma::row_major> fa;
    wmma::fragment<wmma::matrix_b, 16, 16, 8, wmma::precision::tf32, wmma::col_major> fb;
    wmma::fragment<wmma::accumulator, 16, 16, 8, float> acc0, acc1;
    wmma::fill_fragment(acc0, 0.0f);
    wmma::fill_fragment(acc1, 0.0f);

    // Register prefetch: per group-chunk 144 rows x 16 float4 = 2304 / 288 thr = 8
    float4 pf[8];

    auto load_chunk = [&](int c) {
        #pragma unroll
        for (int u = 0; u < 8; u++) {
            const int i = tidg + u * 288;       // 0..2303
            const int n = i >> 4;
            const int f = i & 15;
            const int j = t0 - PAD_ + n;
            float4 v = make_float4(0.f, 0.f, 0.f, 0.f);
            if (j >= 0 && j < T_)
                v = *(const float4*)(histb + (size_t)j * NBINS_ + kbase + c * KC_ + f * 4);
            pf[u] = v;
        }
    };

    auto store_chunk = [&](float* buf) {
        #pragma unroll
        for (int u = 0; u < 8; u++) {
            const int i = tidg + u * 288;
            const int n = i >> 4;
            const int f = i & 15;
            float4 v = pf[u];
            v.x = wmma::__float_to_tf32(v.x);
            v.y = wmma::__float_to_tf32(v.y);
            v.z = wmma::__float_to_tf32(v.z);
            v.w = wmma::__float_to_tf32(v.w);
            *(float4*)(buf + n * YS_LD + f * 4) = v;
        }
    };

    load_chunk(0);
    int buf = 0;

    #pragma unroll 1
    for (int c = 0; c < NCHG_; c++) {
        float* Y = Ysg + buf * JT_ * YS_LD;
        store_chunk(Y);
        // group-private barrier (id 1 or 2), 288 threads
        asm volatile("bar.sync %0, %1;" :: "r"(gid + 1), "r"(288) : "memory");
        if (c < NCHG_ - 1) load_chunk(c + 1);   // LDGs overlap MMA below

        #pragma unroll
        for (int kk = 0; kk < KC_ / 8; kk++) {
            wmma::load_matrix_sync(fb, Y + n0 * YS_LD + kk * 8, YS_LD);
            wmma::load_matrix_sync(fa, Y + PAD_ * YS_LD + kk * 8, YS_LD);        // m 0..15
            wmma::mma_sync(acc0, fa, fb, acc0);
            wmma::load_matrix_sync(fa, Y + (PAD_ + 16) * YS_LD + kk * 8, YS_LD); // m 16..31
            wmma::mma_sync(acc1, fa, fb, acc1);
        }
        buf ^= 1;
    }

    wmma::store_matrix_sync(simsg + 0 * SIMS_LD + n0,  acc0, SIMS_LD, wmma::mem_row_major);
    wmma::store_matrix_sync(simsg + 16 * SIMS_LD + n0, acc1, SIMS_LD, wmma::mem_row_major);
    __syncthreads();

    // ---------------- epilogue GEMM: out = relu(win @ W + b) ----------------
    // win[32][104]: win[c][l] = sims0[c][c+l]+sims1[c][c+l] (l<101), bias row at 101
    // Wsm[104][132]: rows 0..100 = fc_w, row 101 = fc_b, rows 102,103 = 0
    float* win = ys_base;                       // reuse Ys region
    float* Wsm = ys_base + TT_ * WIN_LD;

    const float* s0 = sims_base;
    const float* s1 = sims_base + TT_ * SIMS_LD;
    for (int i = tid; i < TT_ * WIN_LD; i += NTHREADS_) {
        const int c = i / WIN_LD;
        const int l = i - c * WIN_LD;
        float v = 0.f;
        if (l < LOOKUP_)
            v = s0[c * SIMS_LD + c + l] + s1[c * SIMS_LD + c + l];
        else if (l == LOOKUP_)
            v = 1.0f;                           // bias row selector
        win[i] = wmma::__float_to_tf32(v);
    }
    for (int i = tid; i < WIN_LD * ODIM_; i += NTHREADS_) {
        const int l = i >> 7;
        const int o = i & 127;
        float v = 0.f;
        if (l < LOOKUP_)       v = fc_w[l * ODIM_ + o];
        else if (l == LOOKUP_) v = fc_b[o];
        Wsm[l * W_LD + o] = wmma::__float_to_tf32(v);
    }
    __syncthreads();

    const int w = tid >> 5;                     // 0..17
    if (w < 16) {
        const int m0e = (w & 1) * 16;
        const int n0e = (w >> 1) * 16;

        wmma::fragment<wmma::matrix_a, 16, 16, 8, wmma::precision::tf32, wmma::row_major> ea;
        wmma::fragment<wmma::matrix_b, 16, 16, 8, wmma::precision::tf32, wmma::row_major> eb;
        wmma::fragment<wmma::accumulator, 16, 16, 8, float> ec;
        wmma::fill_fragment(ec, 0.0f);

        #pragma unroll
        for (int kk = 0; kk < WIN_LD / 8; kk++) {       // 13 k-steps
            wmma::load_matrix_sync(ea, win + m0e * WIN_LD + kk * 8, WIN_LD);
            wmma::load_matrix_sync(eb, Wsm + kk * 8 * W_LD + n0e, W_LD);
            wmma::mma_sync(ec, ea, eb, ec);
        }
        #pragma unroll
        for (int i = 0; i < ec.num_elements; i++)
            ec.x[i] = fmaxf(ec.x[i], 0.0f);

        float* op = out + ((size_t)b * T_ + t0 + m0e) * ODIM_ + n0e;
        wmma::store_matrix_sync(op, ec, ODIM_, wmma::mem_row_major);
    }
}

// ---------------------------------------------------------------------------
extern "C" void kernel_launch(void* const* d_in, const int* in_sizes, int n_in,
                              void* d_out, int out_size)
{
    const int*   frames = (const int*)d_in[0];
    const float* fc_w   = (const float*)d_in[1];
    const float* fc_b   = (const float*)d_in[2];
    float*       out    = (float*)d_out;

    // idempotent; non-stream API (capture-safe)
    cudaFuncSetAttribute(band_fc_v3,
                         cudaFuncAttributeMaxDynamicSharedMemorySize, SMEM_BYTES);

    hist_kernel<<<B_ * T_, 256>>>(frames);

    dim3 grid(T_ / TT_, B_);
    band_fc_v3<<<grid, NTHREADS_, SMEM_BYTES>>>(fc_w, fc_b, out);
}

// round 6
// speedup vs baseline: 1.9901x; 1.3575x over previous
#include <cstdint>
#include <cuda_runtime.h>
#include <cuda_bf16.h>
#include <mma.h>

using namespace nvcuda;

// Problem constants
#define B_     4
#define T_     1024
#define HW_    1296            // 27*48
#define NBINS_ 512
#define LOOKUP_ 101
#define PAD_   50
#define ODIM_  128
#define TT_    32              // centers per block
#define JT_    144             // neighbor rows per block (n range, 9x16)
#define KC_    32              // k-chunk (floats) per pipeline stage
#define YS_LD  36              // Ys row stride (floats): 32 + 4 pad -> conflict-free
#define SIMS_LD 136            // 132 used cols + pad
#define WIN_LD 104             // 101 + bias row + pad
#define W_LD   132
#define NGROUPS_ 4             // k-split groups (128 bins each)
#define GTHREADS_ 160          // threads per group (5 warps)
#define NTHREADS_ 640

#define YS_TOT   (NGROUPS_ * 2 * JT_ * YS_LD)      // 41472 floats
#define SIMS_TOT (2 * TT_ * SIMS_LD)               // 8704 floats
#define SMEM_BYTES ((YS_TOT + SIMS_TOT) * 4)       // 200704 B

// Scratch: normalized histograms (tf32-rounded), (B*T, 512) fp32 = 8 MB
__device__ float g_hist[B_ * T_ * NBINS_];

// ---------------------------------------------------------------------------
// Kernel 1: per-frame 512-bin RGB histogram + L2 normalize (+ tf32 round)
// ---------------------------------------------------------------------------
__global__ __launch_bounds__(256) void hist_kernel(const int* __restrict__ frames)
{
    __shared__ unsigned int h[NBINS_];
    __shared__ float red[8];

    const int bt = blockIdx.x;
    const int tid = threadIdx.x;
    const int* f = frames + (size_t)bt * HW_ * 3;

    #pragma unroll
    for (int i = tid; i < NBINS_; i += 256) h[i] = 0u;
    __syncthreads();

    for (int grp = tid; grp < HW_ / 4; grp += 256) {
        const int4* p4 = (const int4*)(f + grp * 12);
        int4 v0 = p4[0];
        int4 v1 = p4[1];
        int4 v2 = p4[2];
        int b0 = ((v0.x >> 5) << 6) | ((v0.y >> 5) << 3) | (v0.z >> 5);
        int b1 = ((v0.w >> 5) << 6) | ((v1.x >> 5) << 3) | (v1.y >> 5);
        int b2 = ((v1.z >> 5) << 6) | ((v1.w >> 5) << 3) | (v2.x >> 5);
        int b3 = ((v2.y >> 5) << 6) | ((v2.z >> 5) << 3) | (v2.w >> 5);
        atomicAdd(&h[b0], 1u);
        atomicAdd(&h[b1], 1u);
        atomicAdd(&h[b2], 1u);
        atomicAdd(&h[b3], 1u);
    }
    __syncthreads();

    float s = 0.f;
    #pragma unroll
    for (int i = tid; i < NBINS_; i += 256) {
        float v = (float)h[i];
        s += v * v;
    }
    #pragma unroll
    for (int o = 16; o; o >>= 1) s += __shfl_down_sync(0xffffffffu, s, o);
    if ((tid & 31) == 0) red[tid >> 5] = s;
    __syncthreads();
    if (tid == 0) {
        float t = 0.f;
        #pragma unroll
        for (int i = 0; i < 8; i++) t += red[i];
        red[0] = 1.0f / fmaxf(sqrtf(t), 1e-12f);
    }
    __syncthreads();
    const float inv = red[0];

    float* dst = g_hist + (size_t)bt * NBINS_;
    #pragma unroll
    for (int i = tid; i < NBINS_; i += 256)
        dst[i] = wmma::__float_to_tf32((float)h[i] * inv);   // pre-round for mma
}

// ---------------------------------------------------------------------------
// cp.async helper (16B, L2-only, zero-fill when src_bytes==0)
// ---------------------------------------------------------------------------
__device__ __forceinline__ void cp_async16(unsigned int dst, const void* src, int src_bytes)
{
    asm volatile("cp.async.cg.shared.global [%0], [%1], 16, %2;"
                 :: "r"(dst), "l"(src), "r"(src_bytes) : "memory");
}

// ---------------------------------------------------------------------------
// One k-chunk (32 bins) of band MMA for one warp.
// Warp covers M=32 (2 m16 tiles) x NT n8-tiles starting at n0w.
// Fragment layout (mma.m16n8k8.row.col): g = lane>>2, t = lane&3.
// ---------------------------------------------------------------------------
template<int NT>
__device__ __forceinline__ void band_chunk(const float* __restrict__ Y,
                                           float (&acc)[2][4][4],
                                           int n0w, int g, int t)
{
    #pragma unroll
    for (int kk = 0; kk < KC_ / 8; kk++) {
        const int k0 = kk * 8;
        unsigned a[2][4];
        #pragma unroll
        for (int mi = 0; mi < 2; mi++) {
            const float* r0 = Y + (PAD_ + mi * 16 + g) * YS_LD + k0 + t;
            const float* r1 = Y + (PAD_ + mi * 16 + 8 + g) * YS_LD + k0 + t;
            a[mi][0] = __float_as_uint(r0[0]);
            a[mi][1] = __float_as_uint(r1[0]);
            a[mi][2] = __float_as_uint(r0[4]);
            a[mi][3] = __float_as_uint(r1[4]);
        }
        #pragma unroll
        for (int nj = 0; nj < NT; nj++) {
            const float* rb = Y + (n0w + nj * 8 + g) * YS_LD + k0 + t;
            unsigned b0 = __float_as_uint(rb[0]);
            unsigned b1 = __float_as_uint(rb[4]);
            #pragma unroll
            for (int mi = 0; mi < 2; mi++) {
                asm volatile(
                    "mma.sync.aligned.m16n8k8.row.col.f32.tf32.tf32.f32 "
                    "{%0,%1,%2,%3},{%4,%5,%6,%7},{%8,%9},{%0,%1,%2,%3};"
                    : "+f"(acc[mi][nj][0]), "+f"(acc[mi][nj][1]),
                      "+f"(acc[mi][nj][2]), "+f"(acc[mi][nj][3])
                    : "r"(a[mi][0]), "r"(a[mi][1]), "r"(a[mi][2]), "r"(a[mi][3]),
                      "r"(b0), "r"(b1));
            }
        }
    }
}

// ---------------------------------------------------------------------------
// Kernel 2: banded similarity (explicit tf32 mma, 4-way k-split, cp.async
//           double-buffer) + FC(101->128)+bias+ReLU as tf32 wmma GEMM
// ---------------------------------------------------------------------------
__global__ __launch_bounds__(NTHREADS_, 1) void band_fc_v4(
    const float* __restrict__ fc_w,   // (101,128)
    const float* __restrict__ fc_b,   // (128,)
    float* __restrict__ out)          // (B,T,128)
{
    extern __shared__ float smem[];
    float* ys_base   = smem;                       // [4][2][144][36]
    float* sims_base = smem + YS_TOT;              // [2][32][136]

    const int tid  = threadIdx.x;
    const int b    = blockIdx.y;
    const int t0   = blockIdx.x * TT_;
    const float* histb = g_hist + (size_t)b * T_ * NBINS_;

    const int gid   = tid / GTHREADS_;             // k-group 0..3
    const int tidg  = tid - gid * GTHREADS_;
    const int warpg = tidg >> 5;                   // 0..4
    const int lane  = tidg & 31;
    const int g     = lane >> 2;
    const int t     = lane & 3;
    const int kbase = gid * 128;

    float* Ysg = ys_base + gid * 2 * JT_ * YS_LD;
    const unsigned int ys_u32 = (unsigned int)__cvta_generic_to_shared(Ysg);

    // ---- cp.async chunk issue: 144 rows x 8 float4 = 1152 ops / 160 thr ----
    auto issue = [&](int cc, int bufi) {
        const float* srcbase = histb + kbase + cc * KC_;
        const unsigned int dstbase = ys_u32 + (unsigned int)(bufi * JT_ * YS_LD * 4);
        #pragma unroll
        for (int u = 0; u < 8; u++) {
            const int i = tidg + u * GTHREADS_;
            if (i < JT_ * 8) {
                const int r = i >> 3;
                const int f = i & 7;
                const int j = t0 - PAD_ + r;
                const int jc = min(max(j, 0), T_ - 1);
                const float* src = srcbase + (size_t)jc * NBINS_ + f * 4;
                const int sz = (j >= 0 && j < T_) ? 16 : 0;
                cp_async16(dstbase + (unsigned int)((r * YS_LD + f * 4) * 4), src, sz);
            }
        }
        asm volatile("cp.async.commit_group;" ::: "memory");
    };

    float acc[2][4][4] = {};

    issue(0, 0);
    issue(1, 1);

    #pragma unroll 1
    for (int c = 0; c < 4; c++) {
        if (c < 3) asm volatile("cp.async.wait_group 1;" ::: "memory");
        else       asm volatile("cp.async.wait_group 0;" ::: "memory");
        asm volatile("bar.sync %0, %1;" :: "r"(gid + 1), "r"(GTHREADS_) : "memory");

        const float* Y = Ysg + (c & 1) * JT_ * YS_LD;
        if (warpg < 4) band_chunk<4>(Y, acc, warpg * 32, g, t);
        else           band_chunk<2>(Y, acc, 128, g, t);

        asm volatile("bar.sync %0, %1;" :: "r"(gid + 1), "r"(GTHREADS_) : "memory");
        if (c < 2) issue(c + 2, c & 1);
    }

    // ---- merge 4 groups into 2 sims buffers ----
    const int nt = (warpg < 4) ? 4 : 2;
    const int n0w = warpg * 32;
    float* sbuf = sims_base + (gid & 1) * TT_ * SIMS_LD;

    if (gid < 2) {
        for (int mi = 0; mi < 2; mi++)
            for (int nj = 0; nj < nt; nj++) {
                const int col = n0w + nj * 8 + 2 * t;
                if (col < 132) {
                    #pragma unroll
                    for (int h = 0; h < 2; h++) {
                        const int row = mi * 16 + g + h * 8;
                        *(float2*)(sbuf + row * SIMS_LD + col) =
                            make_float2(acc[mi][nj][2 * h], acc[mi][nj][2 * h + 1]);
                    }
                }
            }
    }
    __syncthreads();
    if (gid >= 2) {
        for (int mi = 0; mi < 2; mi++)
            for (int nj = 0; nj < nt; nj++) {
                const int col = n0w + nj * 8 + 2 * t;
                if (col < 132) {
                    #pragma unroll
                    for (int h = 0; h < 2; h++) {
                        const int row = mi * 16 + g + h * 8;
                        float2* p = (float2*)(sbuf + row * SIMS_LD + col);
                        float2 v = *p;
                        v.x += acc[mi][nj][2 * h];
                        v.y += acc[mi][nj][2 * h + 1];
                        *p = v;
                    }
                }
            }
    }
    __syncthreads();

    // ---------------- epilogue GEMM: out = relu(win @ W + b) ----------------
    float* win = ys_base;                       // reuse Ys region
    float* Wsm = ys_base + TT_ * WIN_LD;
    const float* s0 = sims_base;
    const float* s1 = sims_base + TT_ * SIMS_LD;

    for (int i = tid; i < TT_ * WIN_LD; i += NTHREADS_) {
        const int c = i / WIN_LD;
        const int l = i - c * WIN_LD;
        float v = 0.f;
        if (l < LOOKUP_)
            v = s0[c * SIMS_LD + c + l] + s1[c * SIMS_LD + c + l];
        else if (l == LOOKUP_)
            v = 1.0f;
        win[i] = wmma::__float_to_tf32(v);
    }
    for (int i = tid; i < WIN_LD * ODIM_; i += NTHREADS_) {
        const int l = i >> 7;
        const int o = i & 127;
        float v = 0.f;
        if (l < LOOKUP_)       v = fc_w[l * ODIM_ + o];
        else if (l == LOOKUP_) v = fc_b[o];
        Wsm[l * W_LD + o] = wmma::__float_to_tf32(v);
    }
    __syncthreads();

    const int w = tid >> 5;
    if (w < 16) {
        const int m0e = (w & 1) * 16;
        const int n0e = (w >> 1) * 16;

        wmma::fragment<wmma::matrix_a, 16, 16, 8, wmma::precision::tf32, wmma::row_major> ea;
        wmma::fragment<wmma::matrix_b, 16, 16, 8, wmma::precision::tf32, wmma::row_major> eb;
        wmma::fragment<wmma::accumulator, 16, 16, 8, float> ec;
        wmma::fill_fragment(ec, 0.0f);

        #pragma unroll
        for (int kk = 0; kk < WIN_LD / 8; kk++) {
            wmma::load_matrix_sync(ea, win + m0e * WIN_LD + kk * 8, WIN_LD);
            wmma::load_matrix_sync(eb, Wsm + kk * 8 * W_LD + n0e, W_LD);
            wmma::mma_sync(ec, ea, eb, ec);
        }
        #pragma unroll
        for (int i = 0; i < ec.num_elements; i++)
            ec.x[i] = fmaxf(ec.x[i], 0.0f);

        float* op = out + ((size_t)b * T_ + t0 + m0e) * ODIM_ + n0e;
        wmma::store_matrix_sync(op, ec, ODIM_, wmma::mem_row_major);
    }
}

// ---------------------------------------------------------------------------
extern "C" void kernel_launch(void* const* d_in, const int* in_sizes, int n_in,
                              void* d_out, int out_size)
{
    const int*   frames = (const int*)d_in[0];
    const float* fc_w   = (const float*)d_in[1];
    const float* fc_b   = (const float*)d_in[2];
    float*       out    = (float*)d_out;

    cudaFuncSetAttribute(band_fc_v4,
                         cudaFuncAttributeMaxDynamicSharedMemorySize, SMEM_BYTES);

    hist_kernel<<<B_ * T_, 256>>>(frames);

    dim3 grid(T_ / TT_, B_);
    band_fc_v4<<<grid, NTHREADS_, SMEM_BYTES>>>(fc_w, fc_b, out);
}

// round 7
// speedup vs baseline: 2.1228x; 1.0667x over previous
#include <cstdint>
#include <cuda.h>
#include <cuda_runtime.h>
#include <cuda_bf16.h>
#include <mma.h>

using namespace nvcuda;

// Problem constants
#define B_     4
#define T_     1024
#define HW_    1296            // 27*48
#define NBINS_ 512
#define LOOKUP_ 101
#define PAD_   50
#define ODIM_  128
#define TT_    32              // centers per block
#define JT_    144             // neighbor rows per block
#define KC_    32              // k-chunk (floats) per pipeline stage (128B row)
#define SIMS_LD 136
#define WIN_LD 104
#define W_LD   132
#define NGROUPS_ 4             // k-split groups (128 bins each)
#define GTHREADS_ 160          // 5 warps per group
#define NTHREADS_ 640

#define BUF_FLOATS (JT_ * KC_)                 // 4608 floats = 18432 B (18*1024)
#define YS_TOT   (NGROUPS_ * 2 * BUF_FLOATS)   // 36864 floats
#define SIMS_TOT (2 * TT_ * SIMS_LD)           // 8704 floats
#define SMEM_BYTES ((YS_TOT + SIMS_TOT) * 4 + 64)
#define TMA_BYTES (BUF_FLOATS * 4)

// Scratch: normalized histograms (tf32-rounded), (B*T, 512) fp32 = 8 MB
__device__ float g_hist[B_ * T_ * NBINS_];

// ---------------------------------------------------------------------------
// Kernel 1: per-frame 512-bin RGB histogram + L2 normalize (+ tf32 round)
// (HBM-bound at ~8 us: at roofline, unchanged)
// ---------------------------------------------------------------------------
__global__ __launch_bounds__(256) void hist_kernel(const int* __restrict__ frames)
{
    __shared__ unsigned int h[NBINS_];
    __shared__ float red[8];

    const int bt = blockIdx.x;
    const int tid = threadIdx.x;
    const int* f = frames + (size_t)bt * HW_ * 3;

    #pragma unroll
    for (int i = tid; i < NBINS_; i += 256) h[i] = 0u;
    __syncthreads();

    for (int grp = tid; grp < HW_ / 4; grp += 256) {
        const int4* p4 = (const int4*)(f + grp * 12);
        int4 v0 = p4[0];
        int4 v1 = p4[1];
        int4 v2 = p4[2];
        int b0 = ((v0.x >> 5) << 6) | ((v0.y >> 5) << 3) | (v0.z >> 5);
        int b1 = ((v0.w >> 5) << 6) | ((v1.x >> 5) << 3) | (v1.y >> 5);
        int b2 = ((v1.z >> 5) << 6) | ((v1.w >> 5) << 3) | (v2.x >> 5);
        int b3 = ((v2.y >> 5) << 6) | ((v2.z >> 5) << 3) | (v2.w >> 5);
        atomicAdd(&h[b0], 1u);
        atomicAdd(&h[b1], 1u);
        atomicAdd(&h[b2], 1u);
        atomicAdd(&h[b3], 1u);
    }
    __syncthreads();

    float s = 0.f;
    #pragma unroll
    for (int i = tid; i < NBINS_; i += 256) {
        float v = (float)h[i];
        s += v * v;
    }
    #pragma unroll
    for (int o = 16; o; o >>= 1) s += __shfl_down_sync(0xffffffffu, s, o);
    if ((tid & 31) == 0) red[tid >> 5] = s;
    __syncthreads();
    if (tid == 0) {
        float t = 0.f;
        #pragma unroll
        for (int i = 0; i < 8; i++) t += red[i];
        red[0] = 1.0f / fmaxf(sqrtf(t), 1e-12f);
    }
    __syncthreads();
    const float inv = red[0];

    float* dst = g_hist + (size_t)bt * NBINS_;
    #pragma unroll
    for (int i = tid; i < NBINS_; i += 256)
        dst[i] = wmma::__float_to_tf32((float)h[i] * inv);
}

// ---------------------------------------------------------------------------
// SW128-swizzled Ys element offset: row r (0..143), element kidx (0..31)
// TMA wrote row r (128 B) with 16B-unit index XORed by (r & 7).
// ---------------------------------------------------------------------------
__device__ __forceinline__ int ysw(int r, int kidx)
{
    return r * KC_ + ((((kidx >> 2) ^ (r & 7)) << 2) | (kidx & 3));
}

// ---------------------------------------------------------------------------
// One k-chunk (32 bins) of band MMA for one warp.
// ---------------------------------------------------------------------------
template<int NT>
__device__ __forceinline__ void band_chunk(const float* __restrict__ Y,
                                           float (&acc)[2][4][4],
                                           int n0w, int g, int t)
{
    #pragma unroll
    for (int kk = 0; kk < KC_ / 8; kk++) {
        const int klo = kk * 8 + t;
        const int khi = klo + 4;
        unsigned a[2][4];
        #pragma unroll
        for (int mi = 0; mi < 2; mi++) {
            const int ra = PAD_ + mi * 16 + g;
            const int rb = ra + 8;
            a[mi][0] = __float_as_uint(Y[ysw(ra, klo)]);
            a[mi][1] = __float_as_uint(Y[ysw(rb, klo)]);
            a[mi][2] = __float_as_uint(Y[ysw(ra, khi)]);
            a[mi][3] = __float_as_uint(Y[ysw(rb, khi)]);
        }
        #pragma unroll
        for (int nj = 0; nj < NT; nj++) {
            const int rn = n0w + nj * 8 + g;
            unsigned b0 = __float_as_uint(Y[ysw(rn, klo)]);
            unsigned b1 = __float_as_uint(Y[ysw(rn, khi)]);
            #pragma unroll
            for (int mi = 0; mi < 2; mi++) {
                asm volatile(
                    "mma.sync.aligned.m16n8k8.row.col.f32.tf32.tf32.f32 "
                    "{%0,%1,%2,%3},{%4,%5,%6,%7},{%8,%9},{%0,%1,%2,%3};"
                    : "+f"(acc[mi][nj][0]), "+f"(acc[mi][nj][1]),
                      "+f"(acc[mi][nj][2]), "+f"(acc[mi][nj][3])
                    : "r"(a[mi][0]), "r"(a[mi][1]), "r"(a[mi][2]), "r"(a[mi][3]),
                      "r"(b0), "r"(b1));
            }
        }
    }
}

__device__ __forceinline__ void mbar_wait(unsigned int addr, int phase)
{
    asm volatile(
        "{\n\t"
        ".reg .pred P;\n\t"
        "W%=:\n\t"
        "mbarrier.try_wait.parity.shared.b64 P, [%0], %1;\n\t"
        "@P bra D%=;\n\t"
        "bra W%=;\n\t"
        "D%=:\n\t"
        "}"
        :: "r"(addr), "r"(phase) : "memory");
}

// ---------------------------------------------------------------------------
// Kernel 2: banded similarity (tf32 mma, 4-way k-split, TMA double-buffer)
//           + FC(101->128)+bias+ReLU as tf32 wmma GEMM
// ---------------------------------------------------------------------------
__global__ __launch_bounds__(NTHREADS_, 1) void band_fc_v5(
    const __grid_constant__ CUtensorMap tmap,
    const float* __restrict__ fc_w,   // (101,128)
    const float* __restrict__ fc_b,   // (128,)
    float* __restrict__ out)          // (B,T,128)
{
    extern __shared__ __align__(1024) float smem[];
    float* ys_base   = smem;                        // [4][2][144][32] swizzled
    float* sims_base = smem + YS_TOT;               // [2][32][136]

    const unsigned int smem_u32 = (unsigned int)__cvta_generic_to_shared(smem);
    const unsigned int mbar_u32 = smem_u32 + (YS_TOT + SIMS_TOT) * 4;

    const int tid  = threadIdx.x;
    const int b    = blockIdx.y;
    const int t0   = blockIdx.x * TT_;

    const int gid   = tid / GTHREADS_;              // k-group 0..3
    const int tidg  = tid - gid * GTHREADS_;
    const int warpg = tidg >> 5;                    // 0..4
    const int lane  = tidg & 31;
    const int g     = lane >> 2;
    const int t     = lane & 3;
    const int kbase = gid * 128;

    float* Ysg = ys_base + gid * 2 * BUF_FLOATS;
    const unsigned int ysg_u32 = smem_u32 + (unsigned int)(gid * 2 * TMA_BYTES);

    // init 8 mbarriers (4 groups x 2 buffers)
    if (tid < NGROUPS_ * 2) {
        asm volatile("mbarrier.init.shared.b64 [%0], 1;"
                     :: "r"(mbar_u32 + tid * 8) : "memory");
    }
    __syncthreads();

    auto issue = [&](int cc, int bufi) {
        const unsigned int mb = mbar_u32 + (gid * 2 + bufi) * 8;
        asm volatile("mbarrier.arrive.expect_tx.shared.b64 _, [%0], %1;"
                     :: "r"(mb), "r"(TMA_BYTES) : "memory");
        asm volatile(
            "cp.async.bulk.tensor.3d.shared::cta.global.tile.mbarrier::complete_tx::bytes "
            "[%0], [%1, {%2, %3, %4}], [%5];"
            :: "r"(ysg_u32 + (unsigned int)(bufi * TMA_BYTES)),
               "l"((const void*)&tmap),
               "r"(kbase + cc * KC_), "r"(t0 - PAD_), "r"(b),
               "r"(mb) : "memory");
    };

    float acc[2][4][4] = {};

    if (tidg == 0) { issue(0, 0); issue(1, 1); }

    #pragma unroll 1
    for (int c = 0; c < 4; c++) {
        mbar_wait(mbar_u32 + (gid * 2 + (c & 1)) * 8, (c >> 1) & 1);

        const float* Y = Ysg + (c & 1) * BUF_FLOATS;
        if (warpg < 4) band_chunk<4>(Y, acc, warpg * 32, g, t);
        else           band_chunk<2>(Y, acc, 128, g, t);

        asm volatile("bar.sync %0, %1;" :: "r"(gid + 1), "r"(GTHREADS_) : "memory");
        if (c < 2 && tidg == 0) issue(c + 2, c & 1);
    }

    // ---- merge 4 groups into 2 sims buffers ----
    const int nt  = (warpg < 4) ? 4 : 2;
    const int n0w = warpg * 32;
    float* sbuf = sims_base + (gid & 1) * TT_ * SIMS_LD;

    if (gid < 2) {
        for (int mi = 0; mi < 2; mi++)
            for (int nj = 0; nj < nt; nj++) {
                const int col = n0w + nj * 8 + 2 * t;
                if (col < 132) {
                    #pragma unroll
                    for (int h = 0; h < 2; h++) {
                        const int row = mi * 16 + g + h * 8;
                        *(float2*)(sbuf + row * SIMS_LD + col) =
                            make_float2(acc[mi][nj][2 * h], acc[mi][nj][2 * h + 1]);
                    }
                }
            }
    }
    __syncthreads();
    if (gid >= 2) {
        for (int mi = 0; mi < 2; mi++)
            for (int nj = 0; nj < nt; nj++) {
                const int col = n0w + nj * 8 + 2 * t;
                if (col < 132) {
                    #pragma unroll
                    for (int h = 0; h < 2; h++) {
                        const int row = mi * 16 + g + h * 8;
                        float2* p = (float2*)(sbuf + row * SIMS_LD + col);
                        float2 v = *p;
                        v.x += acc[mi][nj][2 * h];
                        v.y += acc[mi][nj][2 * h + 1];
                        *p = v;
                    }
                }
            }
    }
    __syncthreads();

    // ---------------- epilogue GEMM: out = relu(win @ W + b) ----------------
    float* win = ys_base;                       // reuse Ys region
    float* Wsm = ys_base + TT_ * WIN_LD;
    const float* s0 = sims_base;
    const float* s1 = sims_base + TT_ * SIMS_LD;

    for (int i = tid; i < TT_ * WIN_LD; i += NTHREADS_) {
        const int c = i / WIN_LD;
        const int l = i - c * WIN_LD;
        float v = 0.f;
        if (l < LOOKUP_)
            v = s0[c * SIMS_LD + c + l] + s1[c * SIMS_LD + c + l];
        else if (l == LOOKUP_)
            v = 1.0f;
        win[i] = wmma::__float_to_tf32(v);
    }
    for (int i = tid; i < WIN_LD * ODIM_; i += NTHREADS_) {
        const int l = i >> 7;
        const int o = i & 127;
        float v = 0.f;
        if (l < LOOKUP_)       v = fc_w[l * ODIM_ + o];
        else if (l == LOOKUP_) v = fc_b[o];
        Wsm[l * W_LD + o] = wmma::__float_to_tf32(v);
    }
    __syncthreads();

    const int w = tid >> 5;
    if (w < 16) {
        const int m0e = (w & 1) * 16;
        const int n0e = (w >> 1) * 16;

        wmma::fragment<wmma::matrix_a, 16, 16, 8, wmma::precision::tf32, wmma::row_major> ea;
        wmma::fragment<wmma::matrix_b, 16, 16, 8, wmma::precision::tf32, wmma::row_major> eb;
        wmma::fragment<wmma::accumulator, 16, 16, 8, float> ec;
        wmma::fill_fragment(ec, 0.0f);

        #pragma unroll
        for (int kk = 0; kk < WIN_LD / 8; kk++) {
            wmma::load_matrix_sync(ea, win + m0e * WIN_LD + kk * 8, WIN_LD);
            wmma::load_matrix_sync(eb, Wsm + kk * 8 * W_LD + n0e, W_LD);
            wmma::mma_sync(ec, ea, eb, ec);
        }
        #pragma unroll
        for (int i = 0; i < ec.num_elements; i++)
            ec.x[i] = fmaxf(ec.x[i], 0.0f);

        float* op = out + ((size_t)b * T_ + t0 + m0e) * ODIM_ + n0e;
        wmma::store_matrix_sync(op, ec, ODIM_, wmma::mem_row_major);
    }
}

// ---------------------------------------------------------------------------
typedef CUresult (*EncodeTiledFn)(
    CUtensorMap*, CUtensorMapDataType, cuuint32_t, void*,
    const cuuint64_t*, const cuuint64_t*, const cuuint32_t*, const cuuint32_t*,
    CUtensorMapInterleave, CUtensorMapSwizzle, CUtensorMapL2promotion,
    CUtensorMapFloatOOBfill);

extern "C" void kernel_launch(void* const* d_in, const int* in_sizes, int n_in,
                              void* d_out, int out_size)
{
    const int*   frames = (const int*)d_in[0];
    const float* fc_w   = (const float*)d_in[1];
    const float* fc_b   = (const float*)d_in[2];
    float*       out    = (float*)d_out;

    // Build TMA descriptor for g_hist (host-side, capture-time only).
    void* hist_ptr = nullptr;
    cudaGetSymbolAddress(&hist_ptr, g_hist);

    EncodeTiledFn encode = nullptr;
    cudaDriverEntryPointQueryResult qr;
    cudaGetDriverEntryPoint("cuTensorMapEncodeTiled", (void**)&encode,
                            cudaEnableDefault, &qr);

    CUtensorMap tmap;
    cuuint64_t dims[3]    = {NBINS_, T_, B_};
    cuuint64_t strides[2] = {NBINS_ * 4ull, (cuuint64_t)T_ * NBINS_ * 4ull};
    cuuint32_t box[3]     = {KC_, JT_, 1};
    cuuint32_t es[3]      = {1, 1, 1};
    encode(&tmap, CU_TENSOR_MAP_DATA_TYPE_FLOAT32, 3, hist_ptr,
           dims, strides, box, es,
           CU_TENSOR_MAP_INTERLEAVE_NONE, CU_TENSOR_MAP_SWIZZLE_128B,
           CU_TENSOR_MAP_L2_PROMOTION_L2_128B, CU_TENSOR_MAP_FLOAT_OOB_FILL_NONE);

    cudaFuncSetAttribute(band_fc_v5,
                         cudaFuncAttributeMaxDynamicSharedMemorySize, SMEM_BYTES);

    hist_kernel<<<B_ * T_, 256>>>(frames);

    dim3 grid(T_ / TT_, B_);
    band_fc_v5<<<grid, NTHREADS_, SMEM_BYTES>>>(tmap, fc_w, fc_b, out);
}

// round 8
// speedup vs baseline: 2.2917x; 1.0795x over previous
#include <cstdint>
#include <cuda.h>
#include <cuda_runtime.h>
#include <cuda_bf16.h>
#include <mma.h>

using namespace nvcuda;

// Problem constants
#define B_     4
#define T_     1024
#define HW_    1296
#define NBINS_ 512
#define LOOKUP_ 101
#define PAD_   50
#define ODIM_  128
#define TT_    32              // centers per block
#define JT_    144             // neighbor rows per block
#define KC_    32              // k-chunk floats (128B row)
#define SIMS_LD 136
#define WIN_LD 104
#define W_LD   132
#define NGROUPS_ 4
#define GTHREADS_ 192          // 6 warps per group
#define NTHREADS_ 768
#define WPF_   18              // fc_w prefetch regs per thread

#define BUF_FLOATS (JT_ * KC_)                 // 4608 floats = 18432 B
#define TMA_BYTES (BUF_FLOATS * 4)
#define YS_TOT   (NGROUPS_ * 2 * BUF_FLOATS)   // 36864 floats
#define SIMS_TOT (2 * TT_ * SIMS_LD)           // 8704 floats
#define SMEM_BYTES ((YS_TOT + SIMS_TOT) * 4 + 64)

__device__ float g_hist[B_ * T_ * NBINS_];

// ---------------------------------------------------------------------------
// Kernel 1: per-frame histogram + L2 normalize (+ tf32 round). HBM-bound.
// ---------------------------------------------------------------------------
__global__ __launch_bounds__(256) void hist_kernel(const int* __restrict__ frames)
{
    __shared__ unsigned int h[NBINS_];
    __shared__ float red[8];

    const int bt = blockIdx.x;
    const int tid = threadIdx.x;
    const int* f = frames + (size_t)bt * HW_ * 3;

    #pragma unroll
    for (int i = tid; i < NBINS_; i += 256) h[i] = 0u;
    __syncthreads();

    for (int grp = tid; grp < HW_ / 4; grp += 256) {
        const int4* p4 = (const int4*)(f + grp * 12);
        int4 v0 = p4[0];
        int4 v1 = p4[1];
        int4 v2 = p4[2];
        int b0 = ((v0.x >> 5) << 6) | ((v0.y >> 5) << 3) | (v0.z >> 5);
        int b1 = ((v0.w >> 5) << 6) | ((v1.x >> 5) << 3) | (v1.y >> 5);
        int b2 = ((v1.z >> 5) << 6) | ((v1.w >> 5) << 3) | (v2.x >> 5);
        int b3 = ((v2.y >> 5) << 6) | ((v2.z >> 5) << 3) | (v2.w >> 5);
        atomicAdd(&h[b0], 1u);
        atomicAdd(&h[b1], 1u);
        atomicAdd(&h[b2], 1u);
        atomicAdd(&h[b3], 1u);
    }
    __syncthreads();

    float s = 0.f;
    #pragma unroll
    for (int i = tid; i < NBINS_; i += 256) {
        float v = (float)h[i];
        s += v * v;
    }
    #pragma unroll
    for (int o = 16; o; o >>= 1) s += __shfl_down_sync(0xffffffffu, s, o);
    if ((tid & 31) == 0) red[tid >> 5] = s;
    __syncthreads();
    if (tid == 0) {
        float t = 0.f;
        #pragma unroll
        for (int i = 0; i < 8; i++) t += red[i];
        red[0] = 1.0f / fmaxf(sqrtf(t), 1e-12f);
    }
    __syncthreads();
    const float inv = red[0];

    float* dst = g_hist + (size_t)bt * NBINS_;
    #pragma unroll
    for (int i = tid; i < NBINS_; i += 256)
        dst[i] = wmma::__float_to_tf32((float)h[i] * inv);
}

// ---------------------------------------------------------------------------
__device__ __forceinline__ void mbar_wait(unsigned int addr, int phase)
{
    asm volatile(
        "{\n\t"
        ".reg .pred P;\n\t"
        "W%=:\n\t"
        "mbarrier.try_wait.parity.shared.b64 P, [%0], %1;\n\t"
        "@P bra D%=;\n\t"
        "bra W%=;\n\t"
        "D%=:\n\t"
        "}"
        :: "r"(addr), "r"(phase) : "memory");
}

__device__ __forceinline__ void ldsm_x4(unsigned int addr,
                                        unsigned& r0, unsigned& r1,
                                        unsigned& r2, unsigned& r3)
{
    asm volatile("ldmatrix.sync.aligned.m8n8.x4.shared.b16 {%0,%1,%2,%3}, [%4];"
                 : "=r"(r0), "=r"(r1), "=r"(r2), "=r"(r3) : "r"(addr));
}

__device__ __forceinline__ void ldsm_x2(unsigned int addr,
                                        unsigned& r0, unsigned& r1)
{
    asm volatile("ldmatrix.sync.aligned.m8n8.x2.shared.b16 {%0,%1}, [%2];"
                 : "=r"(r0), "=r"(r1) : "r"(addr));
}

__device__ __forceinline__ void mma_tf32(float (&d)[4],
                                         unsigned a0, unsigned a1, unsigned a2, unsigned a3,
                                         unsigned b0, unsigned b1)
{
    asm volatile(
        "mma.sync.aligned.m16n8k8.row.col.f32.tf32.tf32.f32 "
        "{%0,%1,%2,%3},{%4,%5,%6,%7},{%8,%9},{%0,%1,%2,%3};"
        : "+f"(d[0]), "+f"(d[1]), "+f"(d[2]), "+f"(d[3])
        : "r"(a0), "r"(a1), "r"(a2), "r"(a3), "r"(b0), "r"(b1));
}

// ---------------------------------------------------------------------------
// Kernel 2: banded similarity (ldmatrix + tf32 mma, 4-way k-split, TMA
//           double-buffer) + FC epilogue as tf32 wmma GEMM
// 24 warps = 4 k-groups x 6 warps; warp owns M=32 x 24 n-cols (3 n8-tiles).
// ---------------------------------------------------------------------------
__global__ __launch_bounds__(NTHREADS_, 1) void band_fc_v6(
    const __grid_constant__ CUtensorMap tmap,
    const float* __restrict__ fc_w,   // (101,128)
    const float* __restrict__ fc_b,   // (128,)
    float* __restrict__ out)          // (B,T,128)
{
    extern __shared__ __align__(1024) float smem[];
    float* sims_base = smem + YS_TOT;

    const unsigned int smem_u32 = (unsigned int)__cvta_generic_to_shared(smem);
    const unsigned int mbar_u32 = smem_u32 + (YS_TOT + SIMS_TOT) * 4;

    const int tid  = threadIdx.x;
    const int b    = blockIdx.y;
    const int t0   = blockIdx.x * TT_;

    // ---- fc_w/fc_b prefetch into registers (hides L2 latency behind band) --
    float wreg[WPF_];
    #pragma unroll
    for (int u = 0; u < WPF_; u++) {
        const int i = tid + u * NTHREADS_;
        float v = 0.f;
        if (i < WIN_LD * 128) {
            const int l = i >> 7;
            const int o = i & 127;
            if (l < LOOKUP_)       v = fc_w[l * 128 + o];
            else if (l == LOOKUP_) v = fc_b[o];
        }
        wreg[u] = v;
    }

    const int gid   = tid / GTHREADS_;              // k-group 0..3
    const int tidg  = tid - gid * GTHREADS_;
    const int warpg = tidg >> 5;                    // 0..5
    const int lane  = tidg & 31;
    const int g     = lane >> 2;
    const int t     = lane & 3;
    const int kbase = gid * 128;
    const int n0w   = warpg * 24;                   // 3 n8-tiles per warp

    const unsigned int ysg_u32 = smem_u32 + (unsigned int)(gid * 2 * TMA_BYTES);

    // ---- per-lane ldmatrix row/base precompute (SW128-aware) ----
    const int ri = lane & 7;
    const int q  = lane >> 3;                       // 0..3
    // A x4 (mi=0): matrices {m0..m3} = rows (50.. / 58..) x (klo/khi)
    const int rA = PAD_ + (q & 1) * 8 + ri;
    const unsigned offA = (unsigned)(rA * 128);
    const int xA = rA & 7, cA = q >> 1;
    // B x4: {nj0 klo, nj0 khi, nj1 klo, nj1 khi}
    const int rB4 = n0w + (q >> 1) * 8 + ri;
    const unsigned offB4 = (unsigned)(rB4 * 128);
    const int xB4 = rB4 & 7, cB4 = q & 1;
    // B x2: {nj2 klo, nj2 khi} (lanes 0..15 meaningful)
    const int rB2 = n0w + 16 + ri;
    const unsigned offB2 = (unsigned)(rB2 * 128);
    const int xB2 = rB2 & 7, cB2 = q & 1;

    if (tid < NGROUPS_ * 2) {
        asm volatile("mbarrier.init.shared.b64 [%0], 1;"
                     :: "r"(mbar_u32 + tid * 8) : "memory");
    }
    __syncthreads();

    auto issue = [&](int cc, int bufi) {
        const unsigned int mb = mbar_u32 + (gid * 2 + bufi) * 8;
        asm volatile("mbarrier.arrive.expect_tx.shared.b64 _, [%0], %1;"
                     :: "r"(mb), "r"(TMA_BYTES) : "memory");
        asm volatile(
            "cp.async.bulk.tensor.3d.shared::cta.global.tile.mbarrier::complete_tx::bytes "
            "[%0], [%1, {%2, %3, %4}], [%5];"
            :: "r"(ysg_u32 + (unsigned int)(bufi * TMA_BYTES)),
               "l"((const void*)&tmap),
               "r"(kbase + cc * KC_), "r"(t0 - PAD_), "r"(b),
               "r"(mb) : "memory");
    };

    float acc[2][3][4] = {};

    if (tidg == 0) { issue(0, 0); issue(1, 1); }

    #pragma unroll 1
    for (int c = 0; c < 4; c++) {
        mbar_wait(mbar_u32 + (gid * 2 + (c & 1)) * 8, (c >> 1) & 1);
        const unsigned int Yb = ysg_u32 + (unsigned int)((c & 1) * TMA_BYTES);

        #pragma unroll
        for (int kk = 0; kk < KC_ / 8; kk++) {
            unsigned a[8], bb[6];
            const unsigned uA  = (unsigned)((((2 * kk + cA)  ^ xA)  << 4));
            const unsigned uB4 = (unsigned)((((2 * kk + cB4) ^ xB4) << 4));
            const unsigned uB2 = (unsigned)((((2 * kk + cB2) ^ xB2) << 4));
            ldsm_x4(Yb + offA  + uA,        a[0], a[1], a[2], a[3]);
            ldsm_x4(Yb + offA  + uA + 2048, a[4], a[5], a[6], a[7]);   // mi=1 (+16 rows)
            ldsm_x4(Yb + offB4 + uB4,       bb[0], bb[1], bb[2], bb[3]);
            ldsm_x2(Yb + offB2 + uB2,       bb[4], bb[5]);
            #pragma unroll
            for (int nj = 0; nj < 3; nj++) {
                mma_tf32(acc[0][nj], a[0], a[1], a[2], a[3], bb[2 * nj], bb[2 * nj + 1]);
                mma_tf32(acc[1][nj], a[4], a[5], a[6], a[7], bb[2 * nj], bb[2 * nj + 1]);
            }
        }

        asm volatile("bar.sync %0, %1;" :: "r"(gid + 1), "r"(GTHREADS_) : "memory");
        if (c < 2 && tidg == 0) issue(c + 2, c & 1);
    }

    // ---- merge 4 groups into 2 sims buffers ----
    float* sbuf = sims_base + (gid & 1) * TT_ * SIMS_LD;

    if (gid < 2) {
        #pragma unroll
        for (int mi = 0; mi < 2; mi++)
            #pragma unroll
            for (int nj = 0; nj < 3; nj++) {
                const int col = n0w + nj * 8 + 2 * t;
                if (col < 132) {
                    #pragma unroll
                    for (int h = 0; h < 2; h++) {
                        const int row = mi * 16 + g + h * 8;
                        *(float2*)(sbuf + row * SIMS_LD + col) =
                            make_float2(acc[mi][nj][2 * h], acc[mi][nj][2 * h + 1]);
                    }
                }
            }
    }
    __syncthreads();
    if (gid >= 2) {
        #pragma unroll
        for (int mi = 0; mi < 2; mi++)
            #pragma unroll
            for (int nj = 0; nj < 3; nj++) {
                const int col = n0w + nj * 8 + 2 * t;
                if (col < 132) {
                    #pragma unroll
                    for (int h = 0; h < 2; h++) {
                        const int row = mi * 16 + g + h * 8;
                        float2* p = (float2*)(sbuf + row * SIMS_LD + col);
                        float2 v = *p;
                        v.x += acc[mi][nj][2 * h];
                        v.y += acc[mi][nj][2 * h + 1];
                        *p = v;
                    }
                }
            }
    }
    __syncthreads();

    // ---------------- epilogue GEMM: out = relu(win @ W + b) ----------------
    float* win = smem;                          // reuse Ys region
    float* Wsm = smem + TT_ * WIN_LD;
    const float* s0 = sims_base;
    const float* s1 = sims_base + TT_ * SIMS_LD;

    for (int i = tid; i < TT_ * WIN_LD; i += NTHREADS_) {
        const int c = i / WIN_LD;
        const int l = i - c * WIN_LD;
        float v = 0.f;
        if (l < LOOKUP_)
            v = s0[c * SIMS_LD + c + l] + s1[c * SIMS_LD + c + l];
        else if (l == LOOKUP_)
            v = 1.0f;
        win[i] = wmma::__float_to_tf32(v);
    }
    // stage prefetched W (STS only; LDGs issued at kernel start)
    #pragma unroll
    for (int u = 0; u < WPF_; u++) {
        const int i = tid + u * NTHREADS_;
        if (i < WIN_LD * 128) {
            const int l = i >> 7;
            const int o = i & 127;
            Wsm[l * W_LD + o] = wmma::__float_to_tf32(wreg[u]);
        }
    }
    for (int i = tid; i < WIN_LD * 4; i += NTHREADS_) {   // zero pad cols 128..131
        const int l = i >> 2;
        Wsm[l * W_LD + 128 + (i & 3)] = 0.f;
    }
    __syncthreads();

    const int w = tid >> 5;
    if (w < 16) {
        const int m0e = (w & 1) * 16;
        const int n0e = (w >> 1) * 16;

        wmma::fragment<wmma::matrix_a, 16, 16, 8, wmma::precision::tf32, wmma::row_major> ea;
        wmma::fragment<wmma::matrix_b, 16, 16, 8, wmma::precision::tf32, wmma::row_major> eb;
        wmma::fragment<wmma::accumulator, 16, 16, 8, float> ec;
        wmma::fill_fragment(ec, 0.0f);

        #pragma unroll
        for (int kk = 0; kk < WIN_LD / 8; kk++) {
            wmma::load_matrix_sync(ea, win + m0e * WIN_LD + kk * 8, WIN_LD);
            wmma::load_matrix_sync(eb, Wsm + kk * 8 * W_LD + n0e, W_LD);
            wmma::mma_sync(ec, ea, eb, ec);
        }
        #pragma unroll
        for (int i = 0; i < ec.num_elements; i++)
            ec.x[i] = fmaxf(ec.x[i], 0.0f);

        float* op = out + ((size_t)b * T_ + t0 + m0e) * ODIM_ + n0e;
        wmma::store_matrix_sync(op, ec, ODIM_, wmma::mem_row_major);
    }
}

// ---------------------------------------------------------------------------
typedef CUresult (*EncodeTiledFn)(
    CUtensorMap*, CUtensorMapDataType, cuuint32_t, void*,
    const cuuint64_t*, const cuuint64_t*, const cuuint32_t*, const cuuint32_t*,
    CUtensorMapInterleave, CUtensorMapSwizzle, CUtensorMapL2promotion,
    CUtensorMapFloatOOBfill);

extern "C" void kernel_launch(void* const* d_in, const int* in_sizes, int n_in,
                              void* d_out, int out_size)
{
    const int*   frames = (const int*)d_in[0];
    const float* fc_w   = (const float*)d_in[1];
    const float* fc_b   = (const float*)d_in[2];
    float*       out    = (float*)d_out;

    void* hist_ptr = nullptr;
    cudaGetSymbolAddress(&hist_ptr, g_hist);

    EncodeTiledFn encode = nullptr;
    cudaDriverEntryPointQueryResult qr;
    cudaGetDriverEntryPoint("cuTensorMapEncodeTiled", (void**)&encode,
                            cudaEnableDefault, &qr);

    CUtensorMap tmap;
    cuuint64_t dims[3]    = {NBINS_, T_, B_};
    cuuint64_t strides[2] = {NBINS_ * 4ull, (cuuint64_t)T_ * NBINS_ * 4ull};
    cuuint32_t box[3]     = {KC_, JT_, 1};
    cuuint32_t es[3]      = {1, 1, 1};
    encode(&tmap, CU_TENSOR_MAP_DATA_TYPE_FLOAT32, 3, hist_ptr,
           dims, strides, box, es,
           CU_TENSOR_MAP_INTERLEAVE_NONE, CU_TENSOR_MAP_SWIZZLE_128B,
           CU_TENSOR_MAP_L2_PROMOTION_L2_128B, CU_TENSOR_MAP_FLOAT_OOB_FILL_NONE);

    cudaFuncSetAttribute(band_fc_v6,
                         cudaFuncAttributeMaxDynamicSharedMemorySize, SMEM_BYTES);

    hist_kernel<<<B_ * T_, 256>>>(frames);

    dim3 grid(T_ / TT_, B_);
    band_fc_v6<<<grid, NTHREADS_, SMEM_BYTES>>>(tmap, fc_w, fc_b, out);
}

// round 9
// speedup vs baseline: 2.7710x; 1.2092x over previous
#include <cstdint>
#include <cuda.h>
#include <cuda_runtime.h>
#include <cuda_fp16.h>
#include <cuda_bf16.h>
#include <mma.h>

using namespace nvcuda;

// Problem constants
#define B_     4
#define T_     1024
#define HW_    1296
#define NBINS_ 512
#define LOOKUP_ 101
#define PAD_   50
#define ODIM_  128
#define TT_    32              // centers per block
#define JT_    144             // neighbor rows per block
#define KCH_   64              // k-chunk halfs (128B row)
#define SIMS_LD 136
#define WIN_LD 104
#define W_LD   132
#define NGROUPS_ 4
#define GTHREADS_ 192          // 6 warps per group
#define NTHREADS_ 768
#define WPF_   18              // fc_w prefetch regs per thread

#define BUF_HALFS (JT_ * KCH_)                 // 9216 halfs = 18432 B
#define TMA_BYTES (BUF_HALFS * 2)
#define YS_BYTES  (NGROUPS_ * 2 * TMA_BYTES)   // 147456 B
#define YS_FLOATS (YS_BYTES / 4)
#define SIMS_TOT  (2 * TT_ * SIMS_LD)          // 8704 floats
#define SMEM_BYTES (YS_BYTES + SIMS_TOT * 4 + 64)

// Scratch: normalized histograms in fp16, (B*T, 512) = 4 MB
__device__ __half g_hist_h[B_ * T_ * NBINS_];

// ---------------------------------------------------------------------------
// Kernel 1: per-frame histogram + L2 normalize -> fp16. HBM-bound.
// ---------------------------------------------------------------------------
__global__ __launch_bounds__(256) void hist_kernel(const int* __restrict__ frames)
{
    __shared__ unsigned int h[NBINS_];
    __shared__ float red[8];

    const int bt = blockIdx.x;
    const int tid = threadIdx.x;
    const int* f = frames + (size_t)bt * HW_ * 3;

    #pragma unroll
    for (int i = tid; i < NBINS_; i += 256) h[i] = 0u;
    __syncthreads();

    for (int grp = tid; grp < HW_ / 4; grp += 256) {
        const int4* p4 = (const int4*)(f + grp * 12);
        int4 v0 = p4[0];
        int4 v1 = p4[1];
        int4 v2 = p4[2];
        int b0 = ((v0.x >> 5) << 6) | ((v0.y >> 5) << 3) | (v0.z >> 5);
        int b1 = ((v0.w >> 5) << 6) | ((v1.x >> 5) << 3) | (v1.y >> 5);
        int b2 = ((v1.z >> 5) << 6) | ((v1.w >> 5) << 3) | (v2.x >> 5);
        int b3 = ((v2.y >> 5) << 6) | ((v2.z >> 5) << 3) | (v2.w >> 5);
        atomicAdd(&h[b0], 1u);
        atomicAdd(&h[b1], 1u);
        atomicAdd(&h[b2], 1u);
        atomicAdd(&h[b3], 1u);
    }
    __syncthreads();

    float s = 0.f;
    #pragma unroll
    for (int i = tid; i < NBINS_; i += 256) {
        float v = (float)h[i];
        s += v * v;
    }
    #pragma unroll
    for (int o = 16; o; o >>= 1) s += __shfl_down_sync(0xffffffffu, s, o);
    if ((tid & 31) == 0) red[tid >> 5] = s;
    __syncthreads();
    if (tid == 0) {
        float t = 0.f;
        #pragma unroll
        for (int i = 0; i < 8; i++) t += red[i];
        red[0] = 1.0f / fmaxf(sqrtf(t), 1e-12f);
    }
    __syncthreads();
    const float inv = red[0];

    __half* dst = g_hist_h + (size_t)bt * NBINS_;
    #pragma unroll
    for (int i = tid; i < NBINS_; i += 256)
        dst[i] = __float2half_rn((float)h[i] * inv);
}

// ---------------------------------------------------------------------------
__device__ __forceinline__ void mbar_wait(unsigned int addr, int phase)
{
    asm volatile(
        "{\n\t"
        ".reg .pred P;\n\t"
        "W%=:\n\t"
        "mbarrier.try_wait.parity.shared.b64 P, [%0], %1;\n\t"
        "@P bra D%=;\n\t"
        "bra W%=;\n\t"
        "D%=:\n\t"
        "}"
        :: "r"(addr), "r"(phase) : "memory");
}

__device__ __forceinline__ void ldsm_x4(unsigned int addr,
                                        unsigned& r0, unsigned& r1,
                                        unsigned& r2, unsigned& r3)
{
    asm volatile("ldmatrix.sync.aligned.m8n8.x4.shared.b16 {%0,%1,%2,%3}, [%4];"
                 : "=r"(r0), "=r"(r1), "=r"(r2), "=r"(r3) : "r"(addr));
}

__device__ __forceinline__ void ldsm_x2(unsigned int addr,
                                        unsigned& r0, unsigned& r1)
{
    asm volatile("ldmatrix.sync.aligned.m8n8.x2.shared.b16 {%0,%1}, [%2];"
                 : "=r"(r0), "=r"(r1) : "r"(addr));
}

__device__ __forceinline__ void mma_f16(float (&d)[4],
                                        unsigned a0, unsigned a1, unsigned a2, unsigned a3,
                                        unsigned b0, unsigned b1)
{
    asm volatile(
        "mma.sync.aligned.m16n8k16.row.col.f32.f16.f16.f32 "
        "{%0,%1,%2,%3},{%4,%5,%6,%7},{%8,%9},{%0,%1,%2,%3};"
        : "+f"(d[0]), "+f"(d[1]), "+f"(d[2]), "+f"(d[3])
        : "r"(a0), "r"(a1), "r"(a2), "r"(a3), "r"(b0), "r"(b1));
}

// ---------------------------------------------------------------------------
// Kernel 2: banded similarity (fp16 ldmatrix + m16n8k16 mma, 4-way k-split,
//           TMA, barrier-free mainloop) + FC epilogue as tf32 wmma GEMM
// ---------------------------------------------------------------------------
__global__ __launch_bounds__(NTHREADS_, 1) void band_fc_v7(
    const __grid_constant__ CUtensorMap tmap,
    const float* __restrict__ fc_w,   // (101,128)
    const float* __restrict__ fc_b,   // (128,)
    float* __restrict__ out)          // (B,T,128)
{
    extern __shared__ __align__(1024) float smem[];
    float* sims_base = smem + YS_FLOATS;

    const unsigned int smem_u32 = (unsigned int)__cvta_generic_to_shared(smem);
    const unsigned int mbar_u32 = smem_u32 + YS_BYTES + SIMS_TOT * 4;

    const int tid  = threadIdx.x;
    const int b    = blockIdx.y;
    const int t0   = blockIdx.x * TT_;

    // fc_w/fc_b prefetch into registers (LDGs overlap the whole band phase)
    float wreg[WPF_];
    #pragma unroll
    for (int u = 0; u < WPF_; u++) {
        const int i = tid + u * NTHREADS_;
        float v = 0.f;
        if (i < WIN_LD * 128) {
            const int l = i >> 7;
            const int o = i & 127;
            if (l < LOOKUP_)       v = fc_w[l * 128 + o];
            else if (l == LOOKUP_) v = fc_b[o];
        }
        wreg[u] = v;
    }

    const int gid   = tid / GTHREADS_;              // k-group 0..3 (128 bins each)
    const int tidg  = tid - gid * GTHREADS_;
    const int warpg = tidg >> 5;                    // 0..5
    const int lane  = tidg & 31;
    const int g     = lane >> 2;
    const int t     = lane & 3;
    const int kbase = gid * 128;                    // element offset (halfs)
    const int n0w   = warpg * 24;                   // 3 n8-tiles per warp

    const unsigned int ysg_u32 = smem_u32 + (unsigned int)(gid * 2 * TMA_BYTES);

    // per-lane ldmatrix row/base precompute (SW128-aware; 16B units, 128B rows)
    const int ri = lane & 7;
    const int q  = lane >> 3;                       // 0..3
    const int rA = PAD_ + (q & 1) * 8 + ri;         // A: q&1 -> +8 m-rows, q>>1 -> k+8
    const unsigned offA = (unsigned)(rA * 128);
    const int xA = rA & 7, cA = q >> 1;
    const int rB4 = n0w + (q >> 1) * 8 + ri;        // B x4: ntiles 0,1; q&1 -> k+8
    const unsigned offB4 = (unsigned)(rB4 * 128);
    const int xB4 = rB4 & 7, cB4 = q & 1;
    const int rB2 = n0w + 16 + ri;                  // B x2: ntile 2
    const unsigned offB2 = (unsigned)(rB2 * 128);
    const int xB2 = rB2 & 7, cB2 = q & 1;

    if (tid < NGROUPS_ * 2) {
        asm volatile("mbarrier.init.shared.b64 [%0], 1;"
                     :: "r"(mbar_u32 + tid * 8) : "memory");
    }
    __syncthreads();

    // issue both chunks up front (2 buffers, each used once -> no reuse barrier)
    if (tidg == 0) {
        #pragma unroll
        for (int c = 0; c < 2; c++) {
            const unsigned int mb = mbar_u32 + (gid * 2 + c) * 8;
            asm volatile("mbarrier.arrive.expect_tx.shared.b64 _, [%0], %1;"
                         :: "r"(mb), "r"(TMA_BYTES) : "memory");
            asm volatile(
                "cp.async.bulk.tensor.3d.shared::cta.global.tile.mbarrier::complete_tx::bytes "
                "[%0], [%1, {%2, %3, %4}], [%5];"
                :: "r"(ysg_u32 + (unsigned int)(c * TMA_BYTES)),
                   "l"((const void*)&tmap),
                   "r"(kbase + c * KCH_), "r"(t0 - PAD_), "r"(b),
                   "r"(mb) : "memory");
        }
    }

    float acc[2][3][4] = {};

    #pragma unroll
    for (int c = 0; c < 2; c++) {
        mbar_wait(mbar_u32 + (gid * 2 + c) * 8, 0);
        const unsigned int Yb = ysg_u32 + (unsigned int)(c * TMA_BYTES);

        #pragma unroll
        for (int kk = 0; kk < 4; kk++) {            // 4 x k16 per 64-half chunk
            unsigned a[8], bb[6];
            const unsigned uA  = (unsigned)(((2 * kk + cA)  ^ xA)  << 4);
            const unsigned uB4 = (unsigned)(((2 * kk + cB4) ^ xB4) << 4);
            const unsigned uB2 = (unsigned)(((2 * kk + cB2) ^ xB2) << 4);
            ldsm_x4(Yb + offA  + uA,        a[0], a[1], a[2], a[3]);
            ldsm_x4(Yb + offA  + uA + 2048, a[4], a[5], a[6], a[7]);   // +16 rows
            ldsm_x4(Yb + offB4 + uB4,       bb[0], bb[1], bb[2], bb[3]);
            ldsm_x2(Yb + offB2 + uB2,       bb[4], bb[5]);
            #pragma unroll
            for (int nj = 0; nj < 3; nj++) {
                mma_f16(acc[0][nj], a[0], a[1], a[2], a[3], bb[2 * nj], bb[2 * nj + 1]);
                mma_f16(acc[1][nj], a[4], a[5], a[6], a[7], bb[2 * nj], bb[2 * nj + 1]);
            }
        }
    }

    // ---- merge 4 groups into 2 sims buffers ----
    float* sbuf = sims_base + (gid & 1) * TT_ * SIMS_LD;

    if (gid < 2) {
        #pragma unroll
        for (int mi = 0; mi < 2; mi++)
            #pragma unroll
            for (int nj = 0; nj < 3; nj++) {
                const int col = n0w + nj * 8 + 2 * t;
                if (col < 132) {
                    #pragma unroll
                    for (int h = 0; h < 2; h++) {
                        const int row = mi * 16 + g + h * 8;
                        *(float2*)(sbuf + row * SIMS_LD + col) =
                            make_float2(acc[mi][nj][2 * h], acc[mi][nj][2 * h + 1]);
                    }
                }
            }
    }
    __syncthreads();
    if (gid >= 2) {
        #pragma unroll
        for (int mi = 0; mi < 2; mi++)
            #pragma unroll
            for (int nj = 0; nj < 3; nj++) {
                const int col = n0w + nj * 8 + 2 * t;
                if (col < 132) {
                    #pragma unroll
                    for (int h = 0; h < 2; h++) {
                        const int row = mi * 16 + g + h * 8;
                        float2* p = (float2*)(sbuf + row * SIMS_LD + col);
                        float2 v = *p;
                        v.x += acc[mi][nj][2 * h];
                        v.y += acc[mi][nj][2 * h + 1];
                        *p = v;
                    }
                }
            }
    }
    __syncthreads();

    // ---------------- epilogue GEMM: out = relu(win @ W + b) ----------------
    float* win = smem;                          // reuse Ys region
    float* Wsm = smem + TT_ * WIN_LD;
    const float* s0 = sims_base;
    const float* s1 = sims_base + TT_ * SIMS_LD;

    for (int i = tid; i < TT_ * WIN_LD; i += NTHREADS_) {
        const int c = i / WIN_LD;
        const int l = i - c * WIN_LD;
        float v = 0.f;
        if (l < LOOKUP_)
            v = s0[c * SIMS_LD + c + l] + s1[c * SIMS_LD + c + l];
        else if (l == LOOKUP_)
            v = 1.0f;
        win[i] = wmma::__float_to_tf32(v);
    }
    #pragma unroll
    for (int u = 0; u < WPF_; u++) {
        const int i = tid + u * NTHREADS_;
        if (i < WIN_LD * 128) {
            const int l = i >> 7;
            const int o = i & 127;
            Wsm[l * W_LD + o] = wmma::__float_to_tf32(wreg[u]);
        }
    }
    for (int i = tid; i < WIN_LD * 4; i += NTHREADS_) {   // zero pad cols 128..131
        const int l = i >> 2;
        Wsm[l * W_LD + 128 + (i & 3)] = 0.f;
    }
    __syncthreads();

    const int w = tid >> 5;
    if (w < 16) {
        const int m0e = (w & 1) * 16;
        const int n0e = (w >> 1) * 16;

        wmma::fragment<wmma::matrix_a, 16, 16, 8, wmma::precision::tf32, wmma::row_major> ea;
        wmma::fragment<wmma::matrix_b, 16, 16, 8, wmma::precision::tf32, wmma::row_major> eb;
        wmma::fragment<wmma::accumulator, 16, 16, 8, float> ec;
        wmma::fill_fragment(ec, 0.0f);

        #pragma unroll
        for (int kk = 0; kk < WIN_LD / 8; kk++) {
            wmma::load_matrix_sync(ea, win + m0e * WIN_LD + kk * 8, WIN_LD);
            wmma::load_matrix_sync(eb, Wsm + kk * 8 * W_LD + n0e, W_LD);
            wmma::mma_sync(ec, ea, eb, ec);
        }
        #pragma unroll
        for (int i = 0; i < ec.num_elements; i++)
            ec.x[i] = fmaxf(ec.x[i], 0.0f);

        float* op = out + ((size_t)b * T_ + t0 + m0e) * ODIM_ + n0e;
        wmma::store_matrix_sync(op, ec, ODIM_, wmma::mem_row_major);
    }
}

// ---------------------------------------------------------------------------
typedef CUresult (*EncodeTiledFn)(
    CUtensorMap*, CUtensorMapDataType, cuuint32_t, void*,
    const cuuint64_t*, const cuuint64_t*, const cuuint32_t*, const cuuint32_t*,
    CUtensorMapInterleave, CUtensorMapSwizzle, CUtensorMapL2promotion,
    CUtensorMapFloatOOBfill);

extern "C" void kernel_launch(void* const* d_in, const int* in_sizes, int n_in,
                              void* d_out, int out_size)
{
    const int*   frames = (const int*)d_in[0];
    const float* fc_w   = (const float*)d_in[1];
    const float* fc_b   = (const float*)d_in[2];
    float*       out    = (float*)d_out;

    void* hist_ptr = nullptr;
    cudaGetSymbolAddress(&hist_ptr, g_hist_h);

    EncodeTiledFn encode = nullptr;
    cudaDriverEntryPointQueryResult qr;
    cudaGetDriverEntryPoint("cuTensorMapEncodeTiled", (void**)&encode,
                            cudaEnableDefault, &qr);

    CUtensorMap tmap;
    cuuint64_t dims[3]    = {NBINS_, T_, B_};
    cuuint64_t strides[2] = {NBINS_ * 2ull, (cuuint64_t)T_ * NBINS_ * 2ull};
    cuuint32_t box[3]     = {KCH_, JT_, 1};
    cuuint32_t es[3]      = {1, 1, 1};
    encode(&tmap, CU_TENSOR_MAP_DATA_TYPE_FLOAT16, 3, hist_ptr,
           dims, strides, box, es,
           CU_TENSOR_MAP_INTERLEAVE_NONE, CU_TENSOR_MAP_SWIZZLE_128B,
           CU_TENSOR_MAP_L2_PROMOTION_L2_128B, CU_TENSOR_MAP_FLOAT_OOB_FILL_NONE);

    cudaFuncSetAttribute(band_fc_v7,
                         cudaFuncAttributeMaxDynamicSharedMemorySize, SMEM_BYTES);

    hist_kernel<<<B_ * T_, 256>>>(frames);

    dim3 grid(T_ / TT_, B_);
    band_fc_v7<<<grid, NTHREADS_, SMEM_BYTES>>>(tmap, fc_w, fc_b, out);
}